// round 1
// baseline (speedup 1.0000x reference)
#include <cuda_runtime.h>

#define N_   48
#define W_   16
#define X_   256
#define NW_  (N_ * W_)
#define INF_ 1e30f

// Per-anchor partial results for the triplet-loss global reduction.
__device__ float g_psum[N_];
__device__ int   g_phard[N_];

__global__ void __launch_bounds__(256) triplet_anchor_kernel(
    const float* __restrict__ emb,   // [N, W, X] f32
    const float* __restrict__ lab,   // [N, W]    f32 (0/1)
    float* __restrict__ out)         // [337]     f32
{
    const int i    = blockIdx.x;     // anchor / sample index
    const int tid  = threadIdx.x;
    const int lane = tid & 31;
    const int warp = tid >> 5;

    __shared__ __align__(16) float s_anchor[X_];
    __shared__ float s_dist[NW_];
    __shared__ float s_lab[W_];
    __shared__ float s_dpos[W_];
    __shared__ int   s_npos;
    // per-warp reduction scratch
    __shared__ float s_wsum[8], s_wsp[8], s_wsn[8];
    __shared__ int   s_whard[8], s_waccu[8], s_wcp[8], s_wcn[8];
    __shared__ float s_wmaxv[8], s_wminv[8];
    __shared__ int   s_wmaxi[8], s_wmini[8];

    // ---- load anchor row (sample i, w=0) and labels ----
    s_anchor[tid] = emb[((size_t)i * W_) * X_ + tid];
    if (tid < W_) s_lab[tid] = lab[i * W_ + tid];
    __syncthreads();

    // ---- distances: one warp per column j, dist = sum((a-f)^2) ----
    const float4* a4 = reinterpret_cast<const float4*>(s_anchor);
    for (int j = warp; j < NW_; j += 8) {
        const float4* f4 = reinterpret_cast<const float4*>(emb + (size_t)j * X_);
        float s = 0.f;
        #pragma unroll
        for (int u = 0; u < 2; u++) {
            float4 v = f4[lane + 32 * u];
            float4 a = a4[lane + 32 * u];
            float d;
            d = a.x - v.x; s = fmaf(d, d, s);
            d = a.y - v.y; s = fmaf(d, d, s);
            d = a.z - v.z; s = fmaf(d, d, s);
            d = a.w - v.w; s = fmaf(d, d, s);
        }
        #pragma unroll
        for (int off = 16; off; off >>= 1)
            s += __shfl_xor_sync(0xffffffffu, s, off);
        if (lane == 0) s_dist[j] = s;
    }
    __syncthreads();

    // ---- positive distance list (<= 16 entries) ----
    if (tid == 0) {
        int np = 0;
        for (int w = 0; w < W_; w++)
            if (s_lab[w] > 0.f) s_dpos[np++] = s_dist[i * W_ + w];
        s_npos = np;
    }
    __syncthreads();
    const int npos = s_npos;

    // ---- per-thread accumulation over 3 columns each (768 = 3*256) ----
    float maxPosV = -INF_; int maxPosI = NW_;
    float minNegV =  INF_; int minNegI = NW_;
    float sumPos = 0.f, sumNeg = 0.f;
    int   cntPos = 0, cntNeg = 0;
    float tsum = 0.f; int thard = 0, taccu = 0;

    #pragma unroll
    for (int k = 0; k < 3; k++) {
        int j = tid + k * 256;           // strictly increasing within thread
        float d = s_dist[j];
        int rel = j - i * W_;
        bool inRow  = (rel >= 0) && (rel < W_);
        bool isPos  = inRow && (s_lab[rel] > 0.f);
        bool isAnch = (rel == 0);
        if (isPos) {
            sumPos += d; cntPos++;
            if (d > maxPosV) { maxPosV = d; maxPosI = j; }
        } else if (!isAnch) {
            // negative sample
            sumNeg += d; cntNeg++;
            if (d < minNegV) { minNegV = d; minNegI = j; }
            for (int p = 0; p < npos; p++) {
                float dp = s_dpos[p];
                float v = dp - d + 1.0f;          // (diff + MARGIN), M=1
                tsum  += fmaxf(v, 0.f);
                thard += (v > 1e-16f);
                taccu += (d > dp);
            }
        }
    }

    // ---- warp butterfly reductions (deterministic) ----
    #pragma unroll
    for (int off = 16; off; off >>= 1) {
        tsum   += __shfl_xor_sync(0xffffffffu, tsum,   off);
        sumPos += __shfl_xor_sync(0xffffffffu, sumPos, off);
        sumNeg += __shfl_xor_sync(0xffffffffu, sumNeg, off);
        thard  += __shfl_xor_sync(0xffffffffu, thard,  off);
        taccu  += __shfl_xor_sync(0xffffffffu, taccu,  off);
        cntPos += __shfl_xor_sync(0xffffffffu, cntPos, off);
        cntNeg += __shfl_xor_sync(0xffffffffu, cntNeg, off);
        float mv = __shfl_xor_sync(0xffffffffu, maxPosV, off);
        int   mi = __shfl_xor_sync(0xffffffffu, maxPosI, off);
        if (mv > maxPosV || (mv == maxPosV && mi < maxPosI)) { maxPosV = mv; maxPosI = mi; }
        float nv = __shfl_xor_sync(0xffffffffu, minNegV, off);
        int   ni = __shfl_xor_sync(0xffffffffu, minNegI, off);
        if (nv < minNegV || (nv == minNegV && ni < minNegI)) { minNegV = nv; minNegI = ni; }
    }

    if (lane == 0) {
        s_wsum[warp] = tsum;  s_wsp[warp] = sumPos;  s_wsn[warp] = sumNeg;
        s_whard[warp] = thard; s_waccu[warp] = taccu;
        s_wcp[warp] = cntPos;  s_wcn[warp] = cntNeg;
        s_wmaxv[warp] = maxPosV; s_wmaxi[warp] = maxPosI;
        s_wminv[warp] = minNegV; s_wmini[warp] = minNegI;
    }
    __syncthreads();

    // ---- final combine on thread 0 (fixed order -> deterministic) ----
    if (tid == 0) {
        float Tsum = 0.f, SP = 0.f, SN = 0.f;
        int   H = 0, AC = 0, CP = 0, CN = 0;
        float MV = -INF_; int MI = NW_;
        float mV =  INF_; int mI = NW_;
        for (int w2 = 0; w2 < 8; w2++) {
            Tsum += s_wsum[w2]; SP += s_wsp[w2]; SN += s_wsn[w2];
            H += s_whard[w2]; AC += s_waccu[w2];
            CP += s_wcp[w2];  CN += s_wcn[w2];
            if (s_wmaxv[w2] > MV || (s_wmaxv[w2] == MV && s_wmaxi[w2] < MI)) { MV = s_wmaxv[w2]; MI = s_wmaxi[w2]; }
            if (s_wminv[w2] < mV || (s_wminv[w2] == mV && s_wmini[w2] < mI)) { mV = s_wminv[w2]; mI = s_wmini[w2]; }
        }
        float np = (float)CP, nn = (float)CN;
        float npairs = np * nn;

        out[1 + 0 * N_ + i] = MV;            // max_anchor2pos
        out[1 + 1 * N_ + i] = mV;            // min_anchor2neg
        out[1 + 2 * N_ + i] = mV - MV;       // min_neg2pos
        out[1 + 3 * N_ + i] = (np * SN - nn * SP) / npairs;  // avg_neg2pos

        // neg_idx: rank of argmin-neg column mI among negatives.
        // cumsum(negm)[mI] - 1 == mI - (#excluded columns <= mI)
        int ex = 0;
        for (int w = 0; w < W_; w++) {
            bool excl = (w == 0) || (s_lab[w] > 0.f);   // anchor or positive
            if (excl && (i * W_ + w) <= mI) ex++;
        }
        out[1 + 4 * N_ + i] = (float)(mI - ex);

        // pos_idx: rank of argmax-pos column MI among positives.
        int pr = 0;
        for (int w = 0; w < W_; w++)
            if (s_lab[w] > 0.f && (i * W_ + w) <= MI) pr++;
        out[1 + 5 * N_ + i] = (float)(pr - 1);

        out[1 + 6 * N_ + i] = (float)AC / npairs;  // accu_ratio

        g_psum[i]  = Tsum;
        g_phard[i] = H;
    }
}

__global__ void triplet_finalize_kernel(float* __restrict__ out) {
    if (threadIdx.x == 0) {
        float s = 0.f, h = 0.f;
        for (int i = 0; i < N_; i++) { s += g_psum[i]; h += (float)g_phard[i]; }
        out[0] = s / (h + 1e-16f);
    }
}

extern "C" void kernel_launch(void* const* d_in, const int* in_sizes, int n_in,
                              void* d_out, int out_size) {
    const float* emb = (const float*)d_in[0];   // pred_embeddings [48,16,256]
    const float* lab = (const float*)d_in[1];   // pos_neg_label  [48,16]
    float* out = (float*)d_out;                 // 337 floats

    triplet_anchor_kernel<<<N_, 256>>>(emb, lab, out);
    triplet_finalize_kernel<<<1, 32>>>(out);
}

// round 2
// speedup vs baseline: 1.5867x; 1.5867x over previous
#include <cuda_runtime.h>

#define N_   48
#define W_   16
#define X_   256
#define NW_  (N_ * W_)
#define INF_ 1e30f
#define NWARP 16
#define BLK  (NWARP * 32)

// Per-anchor partials + completion counter for fused final reduction.
__device__ float g_psum[N_];
__device__ int   g_phard[N_];
__device__ int   g_count;       // zero-init at load; reset by finalizing block

__global__ void __launch_bounds__(BLK) triplet_anchor_kernel(
    const float* __restrict__ emb,   // [N, W, X] f32
    const float* __restrict__ lab,   // [N, W]    f32 (0/1)
    float* __restrict__ out)         // [337]     f32
{
    const int i    = blockIdx.x;     // anchor / sample index
    const int tid  = threadIdx.x;
    const int lane = tid & 31;
    const int warp = tid >> 5;

    __shared__ __align__(16) float s_anchor[X_];
    __shared__ float s_dist[NW_];
    __shared__ float s_lab[W_];
    __shared__ float s_dpos[W_];
    __shared__ int   s_npos;
    __shared__ float s_wsum[NWARP], s_wsp[NWARP], s_wsn[NWARP];
    __shared__ int   s_whard[NWARP], s_waccu[NWARP], s_wcp[NWARP], s_wcn[NWARP];
    __shared__ float s_wmaxv[NWARP], s_wminv[NWARP];
    __shared__ int   s_wmaxi[NWARP], s_wmini[NWARP];

    // ---- load anchor row (sample i, w=0) and labels ----
    if (tid < X_) s_anchor[tid] = emb[((size_t)i * W_) * X_ + tid];
    if (tid < W_) s_lab[tid] = lab[i * W_ + tid];
    __syncthreads();

    // ---- anchor chunk lives in registers for the whole distance phase ----
    const float4* a4 = reinterpret_cast<const float4*>(s_anchor);
    const float4 aA = a4[lane];
    const float4 aB = a4[lane + 32];

    // ---- distances: 2 columns per warp-iteration for MLP ----
    // columns j1 = warp + 32*it, j2 = j1 + 16 ; it in [0, 24)
    for (int it = 0; it < NW_ / (2 * NWARP); it++) {
        int j1 = warp + 2 * NWARP * it;
        int j2 = j1 + NWARP;
        const float4* f1 = reinterpret_cast<const float4*>(emb + (size_t)j1 * X_);
        const float4* f2 = reinterpret_cast<const float4*>(emb + (size_t)j2 * X_);
        float4 v1a = f1[lane], v1b = f1[lane + 32];
        float4 v2a = f2[lane], v2b = f2[lane + 32];
        float s1 = 0.f, s2 = 0.f, d;
        d = aA.x - v1a.x; s1 = fmaf(d, d, s1);
        d = aA.y - v1a.y; s1 = fmaf(d, d, s1);
        d = aA.z - v1a.z; s1 = fmaf(d, d, s1);
        d = aA.w - v1a.w; s1 = fmaf(d, d, s1);
        d = aB.x - v1b.x; s1 = fmaf(d, d, s1);
        d = aB.y - v1b.y; s1 = fmaf(d, d, s1);
        d = aB.z - v1b.z; s1 = fmaf(d, d, s1);
        d = aB.w - v1b.w; s1 = fmaf(d, d, s1);
        d = aA.x - v2a.x; s2 = fmaf(d, d, s2);
        d = aA.y - v2a.y; s2 = fmaf(d, d, s2);
        d = aA.z - v2a.z; s2 = fmaf(d, d, s2);
        d = aA.w - v2a.w; s2 = fmaf(d, d, s2);
        d = aB.x - v2b.x; s2 = fmaf(d, d, s2);
        d = aB.y - v2b.y; s2 = fmaf(d, d, s2);
        d = aB.z - v2b.z; s2 = fmaf(d, d, s2);
        d = aB.w - v2b.w; s2 = fmaf(d, d, s2);
        #pragma unroll
        for (int off = 16; off; off >>= 1) {
            s1 += __shfl_xor_sync(0xffffffffu, s1, off);
            s2 += __shfl_xor_sync(0xffffffffu, s2, off);
        }
        if (lane == 0) { s_dist[j1] = s1; s_dist[j2] = s2; }
    }
    __syncthreads();

    // ---- positive distance list (<= 16 entries) ----
    if (tid == 0) {
        int np = 0;
        for (int w = 0; w < W_; w++)
            if (s_lab[w] > 0.f) s_dpos[np++] = s_dist[i * W_ + w];
        s_npos = np;
    }
    __syncthreads();
    const int npos = s_npos;

    // ---- per-thread accumulation: j = tid, and j = tid + 512 (tid < 256) ----
    float maxPosV = -INF_; int maxPosI = NW_;
    float minNegV =  INF_; int minNegI = NW_;
    float sumPos = 0.f, sumNeg = 0.f;
    int   cntPos = 0, cntNeg = 0;
    float tsum = 0.f; int thard = 0, taccu = 0;

    const int nj = (tid < NW_ - BLK) ? 2 : 1;
    for (int k = 0; k < nj; k++) {
        int j = tid + k * BLK;
        float dd = s_dist[j];
        int rel = j - i * W_;
        bool inRow  = (rel >= 0) && (rel < W_);
        bool isPos  = inRow && (s_lab[rel] > 0.f);
        bool isAnch = (rel == 0);
        if (isPos) {
            sumPos += dd; cntPos++;
            if (dd > maxPosV) { maxPosV = dd; maxPosI = j; }
        } else if (!isAnch) {
            sumNeg += dd; cntNeg++;
            if (dd < minNegV) { minNegV = dd; minNegI = j; }
            for (int p = 0; p < npos; p++) {
                float v = s_dpos[p] - dd + 1.0f;   // (diff + MARGIN), M=1
                tsum  += fmaxf(v, 0.f);
                thard += (v > 1e-16f);
                taccu += (s_dpos[p] < dd);
            }
        }
    }

    // ---- warp butterfly reductions (deterministic) ----
    #pragma unroll
    for (int off = 16; off; off >>= 1) {
        tsum   += __shfl_xor_sync(0xffffffffu, tsum,   off);
        sumPos += __shfl_xor_sync(0xffffffffu, sumPos, off);
        sumNeg += __shfl_xor_sync(0xffffffffu, sumNeg, off);
        thard  += __shfl_xor_sync(0xffffffffu, thard,  off);
        taccu  += __shfl_xor_sync(0xffffffffu, taccu,  off);
        cntPos += __shfl_xor_sync(0xffffffffu, cntPos, off);
        cntNeg += __shfl_xor_sync(0xffffffffu, cntNeg, off);
        float mv = __shfl_xor_sync(0xffffffffu, maxPosV, off);
        int   mi = __shfl_xor_sync(0xffffffffu, maxPosI, off);
        if (mv > maxPosV || (mv == maxPosV && mi < maxPosI)) { maxPosV = mv; maxPosI = mi; }
        float nv = __shfl_xor_sync(0xffffffffu, minNegV, off);
        int   ni = __shfl_xor_sync(0xffffffffu, minNegI, off);
        if (nv < minNegV || (nv == minNegV && ni < minNegI)) { minNegV = nv; minNegI = ni; }
    }

    if (lane == 0) {
        s_wsum[warp] = tsum;  s_wsp[warp] = sumPos;  s_wsn[warp] = sumNeg;
        s_whard[warp] = thard; s_waccu[warp] = taccu;
        s_wcp[warp] = cntPos;  s_wcn[warp] = cntNeg;
        s_wmaxv[warp] = maxPosV; s_wmaxi[warp] = maxPosI;
        s_wminv[warp] = minNegV; s_wmini[warp] = minNegI;
    }
    __syncthreads();

    // ---- final combine on thread 0 (fixed order -> deterministic) ----
    if (tid == 0) {
        float Tsum = 0.f, SP = 0.f, SN = 0.f;
        int   H = 0, AC = 0, CP = 0, CN = 0;
        float MV = -INF_; int MI = NW_;
        float mV =  INF_; int mI = NW_;
        for (int w2 = 0; w2 < NWARP; w2++) {
            Tsum += s_wsum[w2]; SP += s_wsp[w2]; SN += s_wsn[w2];
            H += s_whard[w2]; AC += s_waccu[w2];
            CP += s_wcp[w2];  CN += s_wcn[w2];
            if (s_wmaxv[w2] > MV || (s_wmaxv[w2] == MV && s_wmaxi[w2] < MI)) { MV = s_wmaxv[w2]; MI = s_wmaxi[w2]; }
            if (s_wminv[w2] < mV || (s_wminv[w2] == mV && s_wmini[w2] < mI)) { mV = s_wminv[w2]; mI = s_wmini[w2]; }
        }
        float np = (float)CP, nn = (float)CN;
        float npairs = np * nn;

        out[1 + 0 * N_ + i] = MV;            // max_anchor2pos
        out[1 + 1 * N_ + i] = mV;            // min_anchor2neg
        out[1 + 2 * N_ + i] = mV - MV;       // min_neg2pos
        out[1 + 3 * N_ + i] = (np * SN - nn * SP) / npairs;  // avg_neg2pos

        // neg_idx: mI minus #excluded (anchor/positive) columns <= mI
        int ex = 0;
        for (int w = 0; w < W_; w++) {
            bool excl = (w == 0) || (s_lab[w] > 0.f);
            if (excl && (i * W_ + w) <= mI) ex++;
        }
        out[1 + 4 * N_ + i] = (float)(mI - ex);

        // pos_idx: rank of argmax-pos column MI among positives
        int pr = 0;
        for (int w = 0; w < W_; w++)
            if (s_lab[w] > 0.f && (i * W_ + w) <= MI) pr++;
        out[1 + 5 * N_ + i] = (float)(pr - 1);

        out[1 + 6 * N_ + i] = (float)AC / npairs;  // accu_ratio

        g_psum[i]  = Tsum;
        g_phard[i] = H;
        __threadfence();
        int old = atomicAdd(&g_count, 1);
        if (old == N_ - 1) {
            // last block: fixed-order global reduction (deterministic)
            __threadfence();
            float s = 0.f, h = 0.f;
            for (int b = 0; b < N_; b++) { s += g_psum[b]; h += (float)g_phard[b]; }
            out[0] = s / (h + 1e-16f);
            g_count = 0;   // reset for next graph replay
        }
    }
}

extern "C" void kernel_launch(void* const* d_in, const int* in_sizes, int n_in,
                              void* d_out, int out_size) {
    const float* emb = (const float*)d_in[0];   // pred_embeddings [48,16,256]
    const float* lab = (const float*)d_in[1];   // pos_neg_label  [48,16]
    float* out = (float*)d_out;                 // 337 floats

    triplet_anchor_kernel<<<N_, BLK>>>(emb, lab, out);
}

// round 3
// speedup vs baseline: 2.2778x; 1.4356x over previous
#include <cuda_runtime.h>

#define N_    48
#define W_    16
#define X_    256
#define NW_   (N_ * W_)
#define SPLIT 3
#define CPB   (NW_ / SPLIT)      // 256 columns per block
#define INF_  1e30f
#define NWARP 16
#define BLK   (NWARP * 32)       // 512 threads

// Per-(anchor,chunk) partials
__device__ float g_sumPos[N_][SPLIT], g_sumNeg[N_][SPLIT];
__device__ float g_maxV[N_][SPLIT],   g_minV[N_][SPLIT], g_tsum[N_][SPLIT];
__device__ int   g_cntPos[N_][SPLIT], g_cntNeg[N_][SPLIT];
__device__ int   g_maxI[N_][SPLIT],   g_minI[N_][SPLIT];
__device__ int   g_hard[N_][SPLIT],   g_accu[N_][SPLIT];
__device__ int   g_acnt[N_];          // per-anchor completion counters
// Per-anchor partials for the global loss
__device__ float g_psum[N_];
__device__ int   g_phard[N_];
__device__ int   g_count;             // global completion counter

__global__ void __launch_bounds__(BLK) triplet_kernel(
    const float* __restrict__ emb,   // [N, W, X] f32
    const float* __restrict__ lab,   // [N, W]    f32 (0/1)
    float* __restrict__ out)         // [337]     f32
{
    const int i    = blockIdx.x / SPLIT;   // anchor index
    const int c    = blockIdx.x % SPLIT;   // column chunk
    const int col0 = c * CPB;
    const int tid  = threadIdx.x;
    const int lane = tid & 31;
    const int warp = tid >> 5;

    __shared__ __align__(16) float s_anchor[X_];
    __shared__ float s_dist[CPB];
    __shared__ float s_own[W_];            // dist of own-row columns (redundant per block)
    __shared__ float s_lab[W_];
    __shared__ float s_dpos[W_];
    __shared__ int   s_npos;
    __shared__ float s_wsum[8], s_wsp[8], s_wsn[8];
    __shared__ int   s_whard[8], s_waccu[8], s_wcp[8], s_wcn[8];
    __shared__ float s_wmaxv[8], s_wminv[8];
    __shared__ int   s_wmaxi[8], s_wmini[8];

    if (tid < X_) s_anchor[tid] = emb[((size_t)i * W_) * X_ + tid];
    if (tid < W_) s_lab[tid] = lab[i * W_ + tid];
    __syncthreads();

    const float4* a4 = reinterpret_cast<const float4*>(s_anchor);
    const float4 aA = a4[lane];
    const float4 aB = a4[lane + 32];

    // ---- own-row distances (16 columns, one per warp) ----
    {
        const int jg = i * W_ + warp;
        const float4* f = reinterpret_cast<const float4*>(emb + (size_t)jg * X_);
        float4 va = f[lane], vb = f[lane + 32];
        float s = 0.f, d;
        d = aA.x - va.x; s = fmaf(d, d, s);
        d = aA.y - va.y; s = fmaf(d, d, s);
        d = aA.z - va.z; s = fmaf(d, d, s);
        d = aA.w - va.w; s = fmaf(d, d, s);
        d = aB.x - vb.x; s = fmaf(d, d, s);
        d = aB.y - vb.y; s = fmaf(d, d, s);
        d = aB.z - vb.z; s = fmaf(d, d, s);
        d = aB.w - vb.w; s = fmaf(d, d, s);
        #pragma unroll
        for (int off = 16; off; off >>= 1) s += __shfl_xor_sync(0xffffffffu, s, off);
        if (lane == 0) s_own[warp] = s;
    }

    // ---- chunk distances: each warp 16 cols, 4 per iteration (batched loads) ----
    for (int it = 0; it < 4; it++) {
        int jl[4];
        float4 va[4], vb[4];
        #pragma unroll
        for (int u = 0; u < 4; u++) {
            jl[u] = warp + NWARP * (4 * it + u);          // local col in [0, 256)
            const float4* f = reinterpret_cast<const float4*>(
                emb + (size_t)(col0 + jl[u]) * X_);
            va[u] = f[lane]; vb[u] = f[lane + 32];
        }
        float s[4];
        #pragma unroll
        for (int u = 0; u < 4; u++) {
            float acc = 0.f, d;
            d = aA.x - va[u].x; acc = fmaf(d, d, acc);
            d = aA.y - va[u].y; acc = fmaf(d, d, acc);
            d = aA.z - va[u].z; acc = fmaf(d, d, acc);
            d = aA.w - va[u].w; acc = fmaf(d, d, acc);
            d = aB.x - vb[u].x; acc = fmaf(d, d, acc);
            d = aB.y - vb[u].y; acc = fmaf(d, d, acc);
            d = aB.z - vb[u].z; acc = fmaf(d, d, acc);
            d = aB.w - vb[u].w; acc = fmaf(d, d, acc);
            s[u] = acc;
        }
        #pragma unroll
        for (int off = 16; off; off >>= 1) {
            #pragma unroll
            for (int u = 0; u < 4; u++)
                s[u] += __shfl_xor_sync(0xffffffffu, s[u], off);
        }
        if (lane == 0) {
            #pragma unroll
            for (int u = 0; u < 4; u++) s_dist[jl[u]] = s[u];
        }
    }
    __syncthreads();

    // ---- compact positive-distance list ----
    if (tid == 0) {
        int np = 0;
        for (int w = 0; w < W_; w++)
            if (s_lab[w] > 0.f) s_dpos[np++] = s_own[w];
        s_npos = np;
    }
    __syncthreads();
    const int npos = s_npos;

    // ---- pair phase: threads 0..255, one column each ----
    float maxPosV = -INF_; int maxPosI = NW_;
    float minNegV =  INF_; int minNegI = NW_;
    float sumPos = 0.f, sumNeg = 0.f;
    int   cntPos = 0, cntNeg = 0;
    float tsum = 0.f; int thard = 0, taccu = 0;

    if (tid < CPB) {
        const int j  = col0 + tid;      // global column
        const float dd = s_dist[tid];
        const int rel = j - i * W_;
        const bool inRow  = (rel >= 0) && (rel < W_);
        const bool isPos  = inRow && (s_lab[rel] > 0.f);
        const bool isAnch = (rel == 0);
        if (isPos) {
            sumPos = dd; cntPos = 1; maxPosV = dd; maxPosI = j;
        } else if (!isAnch) {
            sumNeg = dd; cntNeg = 1; minNegV = dd; minNegI = j;
            for (int p = 0; p < npos; p++) {
                float dp = s_dpos[p];
                float v = dp - dd + 1.0f;     // (diff + MARGIN), M=1
                tsum  += fmaxf(v, 0.f);
                thard += (v > 1e-16f);
                taccu += (dp < dd);
            }
        }
    }

    // ---- warp butterfly reductions (warps 0..7 hold all data) ----
    if (warp < 8) {
        #pragma unroll
        for (int off = 16; off; off >>= 1) {
            tsum   += __shfl_xor_sync(0xffffffffu, tsum,   off);
            sumPos += __shfl_xor_sync(0xffffffffu, sumPos, off);
            sumNeg += __shfl_xor_sync(0xffffffffu, sumNeg, off);
            thard  += __shfl_xor_sync(0xffffffffu, thard,  off);
            taccu  += __shfl_xor_sync(0xffffffffu, taccu,  off);
            cntPos += __shfl_xor_sync(0xffffffffu, cntPos, off);
            cntNeg += __shfl_xor_sync(0xffffffffu, cntNeg, off);
            float mv = __shfl_xor_sync(0xffffffffu, maxPosV, off);
            int   mi = __shfl_xor_sync(0xffffffffu, maxPosI, off);
            if (mv > maxPosV || (mv == maxPosV && mi < maxPosI)) { maxPosV = mv; maxPosI = mi; }
            float nv = __shfl_xor_sync(0xffffffffu, minNegV, off);
            int   ni = __shfl_xor_sync(0xffffffffu, minNegI, off);
            if (nv < minNegV || (nv == minNegV && ni < minNegI)) { minNegV = nv; minNegI = ni; }
        }
        if (lane == 0) {
            s_wsum[warp] = tsum;  s_wsp[warp] = sumPos;  s_wsn[warp] = sumNeg;
            s_whard[warp] = thard; s_waccu[warp] = taccu;
            s_wcp[warp] = cntPos;  s_wcn[warp] = cntNeg;
            s_wmaxv[warp] = maxPosV; s_wmaxi[warp] = maxPosI;
            s_wminv[warp] = minNegV; s_wmini[warp] = minNegI;
        }
    }
    __syncthreads();

    if (tid == 0) {
        // ---- chunk combine (fixed order, deterministic) ----
        float Tsum = 0.f, SP = 0.f, SN = 0.f;
        int   H = 0, AC = 0, CP = 0, CN = 0;
        float MV = -INF_; int MI = NW_;
        float mV =  INF_; int mI = NW_;
        for (int w2 = 0; w2 < 8; w2++) {
            Tsum += s_wsum[w2]; SP += s_wsp[w2]; SN += s_wsn[w2];
            H += s_whard[w2]; AC += s_waccu[w2];
            CP += s_wcp[w2];  CN += s_wcn[w2];
            if (s_wmaxv[w2] > MV || (s_wmaxv[w2] == MV && s_wmaxi[w2] < MI)) { MV = s_wmaxv[w2]; MI = s_wmaxi[w2]; }
            if (s_wminv[w2] < mV || (s_wminv[w2] == mV && s_wmini[w2] < mI)) { mV = s_wminv[w2]; mI = s_wmini[w2]; }
        }
        g_sumPos[i][c] = SP;  g_sumNeg[i][c] = SN;  g_tsum[i][c] = Tsum;
        g_cntPos[i][c] = CP;  g_cntNeg[i][c] = CN;
        g_maxV[i][c] = MV;    g_maxI[i][c] = MI;
        g_minV[i][c] = mV;    g_minI[i][c] = mI;
        g_hard[i][c] = H;     g_accu[i][c] = AC;
        __threadfence();

        int old = atomicAdd(&g_acnt[i], 1);
        if (old == SPLIT - 1) {
            __threadfence();
            // ---- per-anchor combine over chunks 0,1,2 (fixed order) ----
            float aTsum = 0.f, aSP = 0.f, aSN = 0.f;
            int   aH = 0, aAC = 0, aCP = 0, aCN = 0;
            float aMV = -INF_; int aMI = NW_;
            float amV =  INF_; int amI = NW_;
            for (int cc = 0; cc < SPLIT; cc++) {
                aTsum += *(volatile float*)&g_tsum[i][cc];
                aSP   += *(volatile float*)&g_sumPos[i][cc];
                aSN   += *(volatile float*)&g_sumNeg[i][cc];
                aH    += *(volatile int*)&g_hard[i][cc];
                aAC   += *(volatile int*)&g_accu[i][cc];
                aCP   += *(volatile int*)&g_cntPos[i][cc];
                aCN   += *(volatile int*)&g_cntNeg[i][cc];
                float xv = *(volatile float*)&g_maxV[i][cc];
                int   xi = *(volatile int*)&g_maxI[i][cc];
                if (xv > aMV || (xv == aMV && xi < aMI)) { aMV = xv; aMI = xi; }
                float nv = *(volatile float*)&g_minV[i][cc];
                int   ni = *(volatile int*)&g_minI[i][cc];
                if (nv < amV || (nv == amV && ni < amI)) { amV = nv; amI = ni; }
            }
            g_acnt[i] = 0;   // reset for next replay

            float np = (float)aCP, nn = (float)aCN;
            float npairs = np * nn;

            out[1 + 0 * N_ + i] = aMV;                    // max_anchor2pos
            out[1 + 1 * N_ + i] = amV;                    // min_anchor2neg
            out[1 + 2 * N_ + i] = amV - aMV;              // min_neg2pos
            out[1 + 3 * N_ + i] = (np * aSN - nn * aSP) / npairs;  // avg_neg2pos

            // neg_idx: amI minus #excluded (anchor/positive) columns <= amI
            int ex = 0;
            for (int w = 0; w < W_; w++) {
                bool excl = (w == 0) || (s_lab[w] > 0.f);
                if (excl && (i * W_ + w) <= amI) ex++;
            }
            out[1 + 4 * N_ + i] = (float)(amI - ex);

            // pos_idx: rank of argmax-pos column aMI among positives
            int pr = 0;
            for (int w = 0; w < W_; w++)
                if (s_lab[w] > 0.f && (i * W_ + w) <= aMI) pr++;
            out[1 + 5 * N_ + i] = (float)(pr - 1);

            out[1 + 6 * N_ + i] = (float)aAC / npairs;    // accu_ratio

            g_psum[i]  = aTsum;
            g_phard[i] = aH;
            __threadfence();
            int old2 = atomicAdd(&g_count, 1);
            if (old2 == N_ - 1) {
                __threadfence();
                float s = 0.f, h = 0.f;
                for (int b = 0; b < N_; b++) {
                    s += *(volatile float*)&g_psum[b];
                    h += (float)(*(volatile int*)&g_phard[b]);
                }
                out[0] = s / (h + 1e-16f);
                g_count = 0;   // reset for next replay
            }
        }
    }
}

extern "C" void kernel_launch(void* const* d_in, const int* in_sizes, int n_in,
                              void* d_out, int out_size) {
    const float* emb = (const float*)d_in[0];   // pred_embeddings [48,16,256]
    const float* lab = (const float*)d_in[1];   // pos_neg_label  [48,16]
    float* out = (float*)d_out;                 // 337 floats

    triplet_kernel<<<N_ * SPLIT, BLK>>>(emb, lab, out);
}